// round 14
// baseline (speedup 1.0000x reference)
#include <cuda_runtime.h>
#include <math.h>

#define GDIM 4
#define SDIM 2048
#define TTOT 8192
#define MDIM 1024
#define EDIM 64
#define NBLK 128          // gemm blocks: 64 tokens each

typedef unsigned long long ull;

__device__ int   g_idx[TTOT];
__device__ float g_gate[TTOT];
__device__ int   g_pos[TTOT];
__device__ int   g_counts[GDIM * EDIM];
__device__ float g_proxy[NBLK * EDIM];

// ---------------------------------------------------------------------------
// K1: logits = x @ W (fp32, f32x2 FFMA), softmax, argmax, proxy sums.
// EXACT R6 body (proven 50.7us, bit-identical logits).
// ---------------------------------------------------------------------------
__global__ __launch_bounds__(256, 2)
void k_gemm(const float* __restrict__ x, const float* __restrict__ Wt) {
    __shared__ __align__(16) float xls[64 * 65];
    __shared__ __align__(16) float ws[64 * 64];
    __shared__ float isum[64];

    const int tid = threadIdx.x;
    const int w = tid >> 5;
    const int l = tid & 31;
    const int tb = blockIdx.x * 64;

    ull acc[2][4] = {};

    for (int ch = 0; ch < 16; ++ch) {
        {
            int t = tid >> 2, q = tid & 3;
            const float4* src = (const float4*)(x + (size_t)(tb + t) * MDIM + ch * 64 + q * 16);
            float4 v0 = src[0], v1 = src[1], v2 = src[2], v3 = src[3];
            float* d = &xls[t * 65 + q * 16];
            d[0]=v0.x; d[1]=v0.y; d[2]=v0.z; d[3]=v0.w;
            d[4]=v1.x; d[5]=v1.y; d[6]=v1.z; d[7]=v1.w;
            d[8]=v2.x; d[9]=v2.y; d[10]=v2.z; d[11]=v2.w;
            d[12]=v3.x; d[13]=v3.y; d[14]=v3.z; d[15]=v3.w;
        }
        {
            const float4* src = (const float4*)(Wt + (size_t)(ch * 64) * EDIM);
            float4* dst = (float4*)ws;
#pragma unroll
            for (int j = 0; j < 4; ++j) dst[tid + j * 256] = src[tid + j * 256];
        }
        __syncthreads();

#pragma unroll 8
        for (int mm = 0; mm < 64; ++mm) {
            float xa = xls[l * 65 + mm];
            float xb = xls[(l + 32) * 65 + mm];
            ull xa2, xb2;
            asm("mov.b64 %0, {%1, %1};" : "=l"(xa2) : "f"(xa));
            asm("mov.b64 %0, {%1, %1};" : "=l"(xb2) : "f"(xb));
            const ull* wp = (const ull*)&ws[mm * 64 + w * 8];
#pragma unroll
            for (int p = 0; p < 4; ++p) {
                ull w2 = wp[p];
                asm("fma.rn.f32x2 %0, %1, %2, %0;" : "+l"(acc[0][p]) : "l"(w2), "l"(xa2));
                asm("fma.rn.f32x2 %0, %1, %2, %0;" : "+l"(acc[1][p]) : "l"(w2), "l"(xb2));
            }
        }
        __syncthreads();
    }

#pragma unroll
    for (int tt = 0; tt < 2; ++tt) {
        int t = l + 32 * tt;
#pragma unroll
        for (int p = 0; p < 4; ++p) {
            float lo, hi;
            asm("mov.b64 {%0, %1}, %2;" : "=f"(lo), "=f"(hi) : "l"(acc[tt][p]));
            xls[t * 65 + w * 8 + 2 * p]     = lo;
            xls[t * 65 + w * 8 + 2 * p + 1] = hi;
        }
    }
    __syncthreads();

    if (tid < 64) {
        const int t = tid;
        float mx = -1e30f; int am = 0;
        for (int e = 0; e < EDIM; ++e) {
            float v = xls[t * 65 + e];
            if (v > mx) { mx = v; am = e; }
        }
        float sm = 0.0f;
        for (int e = 0; e < EDIM; ++e) {
            float p = expf(xls[t * 65 + e] - mx);
            xls[t * 65 + e] = p;
            sm += p;
        }
        float inv = 1.0f / sm;
        isum[t] = inv;
        g_idx[tb + t]  = am;
        g_gate[tb + t] = inv;
    }
    __syncthreads();

    if (tid < 64) {
        const int e = tid;
        float s = 0.0f;
        for (int t = 0; t < 64; ++t) s += xls[t * 65 + e] * isum[t];
        g_proxy[blockIdx.x * 64 + e] = s;
    }
}

// ---------------------------------------------------------------------------
// K2: exclusive running position within each (group, expert). (R6 exact)
// ---------------------------------------------------------------------------
__global__ __launch_bounds__(1024, 1)
void k_pos() {
    __shared__ int idx_s[2048];
    __shared__ int cnt_s[16 * 64];
    __shared__ int pos_s[2048];

    const int g = blockIdx.x;
    const int tid = threadIdx.x;

    idx_s[tid]        = g_idx[g * 2048 + tid];
    idx_s[tid + 1024] = g_idx[g * 2048 + tid + 1024];
    __syncthreads();

    const int c = tid >> 6;
    const int e = tid & 63;

    int cnt = 0;
#pragma unroll 8
    for (int i = 0; i < 128; ++i) cnt += (idx_s[c * 128 + i] == e);
    cnt_s[c * 64 + e] = cnt;
    __syncthreads();

    int pre = 0;
    for (int cc = 0; cc < c; ++cc) pre += cnt_s[cc * 64 + e];
    if (c == 15) g_counts[g * 64 + e] = pre + cnt;

    int run = pre;
#pragma unroll 4
    for (int i = 0; i < 128; ++i) {
        int s = c * 128 + i;
        if (idx_s[s] == e) pos_s[s] = run++;
    }
    __syncthreads();

    g_pos[g * 2048 + tid]        = pos_s[tid];
    g_pos[g * 2048 + tid + 1024] = pos_s[tid + 1024];
}

// ---------------------------------------------------------------------------
// K3: pure zero-fill, one contiguous 40KB row per block (no routing dep).
// Same structure that hit ~7.3TB/s in R6; minimal smem -> occ 8.
// ---------------------------------------------------------------------------
__global__ __launch_bounds__(256, 8)
void k_zero_rows(float4* __restrict__ out) {
    const size_t base = (size_t)blockIdx.x * 2560;   // 2560 float4 = 40KB
    const float4 z = make_float4(0.f, 0.f, 0.f, 0.f);
#pragma unroll 10
    for (int f = threadIdx.x; f < 2560; f += 256) __stcs(out + base + f, z);
}

// ---------------------------------------------------------------------------
// K4: scatter kept tokens (write-only 4B stores) + aux loss (last block).
// ---------------------------------------------------------------------------
__global__ __launch_bounds__(256, 4)
void k_scatter_aux(float* __restrict__ out, int C, size_t N) {
    const int tid = threadIdx.x;

    if (blockIdx.x < 32) {
        int t = blockIdx.x * 256 + tid;
        int p = g_pos[t];
        if (p < C) {
            size_t base = ((size_t)t * EDIM + g_idx[t]) * (size_t)C + p;
            out[base]     = g_gate[t];
            out[N + base] = 1.0f;
        }
    } else {
        __shared__ float red[256];
        const int g = tid >> 6;
        const int e = tid & 63;
        float px = 0.0f;
        for (int b = 0; b < 32; ++b) px += g_proxy[(g * 32 + b) * 64 + e];
        const float denom = 1.0f + 1e-6f;
        float d1 = ((float)g_counts[g * 64 + e] / (float)SDIM) / denom;
        float dp = (px / (float)SDIM) / denom;
        red[tid] = d1 * dp;
        __syncthreads();
        for (int s = 128; s > 0; s >>= 1) {
            if (tid < s) red[tid] += red[tid + s];
            __syncthreads();
        }
        if (tid == 0)
            out[2 * N] = (red[0] / 256.0f) * ((float)EDIM * (float)EDIM * 0.01f);
    }
}

// ---------------------------------------------------------------------------
// Side stream + events (created once, outside capture / mem checkpoints).
// ---------------------------------------------------------------------------
struct SideStream {
    cudaStream_t s2;
    cudaEvent_t evF, evJ;
    SideStream() {
        cudaStreamCreateWithFlags(&s2, cudaStreamNonBlocking);
        cudaEventCreateWithFlags(&evF, cudaEventDisableTiming);
        cudaEventCreateWithFlags(&evJ, cudaEventDisableTiming);
    }
};
static SideStream g_ss;

extern "C" void kernel_launch(void* const* d_in, const int* in_sizes, int n_in,
                              void* d_out, int out_size) {
    const float* x  = (const float*)d_in[0];
    const float* Wt = (const float*)d_in[1];
    float* out = (float*)d_out;

    size_t N = ((size_t)out_size - 1) / 2;
    int C = (int)(N / ((size_t)TTOT * EDIM));   // 160
    int nrows = (int)((2 * N) / (size_t)(EDIM * C));   // 16384

    // fork: routing chain on side stream, fill on main stream
    cudaEventRecord(g_ss.evF, 0);
    cudaStreamWaitEvent(g_ss.s2, g_ss.evF, 0);

    k_zero_rows<<<nrows, 256>>>((float4*)d_out);        // ~92us, no deps

    k_gemm<<<NBLK, 256, 0, g_ss.s2>>>(x, Wt);           // ~51us, hidden
    k_pos<<<GDIM, 1024, 0, g_ss.s2>>>();
    cudaEventRecord(g_ss.evJ, g_ss.s2);

    cudaStreamWaitEvent(0, g_ss.evJ, 0);
    k_scatter_aux<<<33, 256>>>(out, C, N);              // patch + aux
}

// round 15
// speedup vs baseline: 1.3072x; 1.3072x over previous
#include <cuda_runtime.h>
#include <math.h>

#define GDIM 4
#define SDIM 2048
#define TTOT 8192
#define MDIM 1024
#define EDIM 64
#define NBLK 128          // gemm blocks: 64 tokens each

typedef unsigned long long ull;

__device__ int   g_idx[TTOT];
__device__ float g_gate[TTOT];
__device__ int   g_pos[TTOT];
__device__ int   g_counts[GDIM * EDIM];
__device__ float g_proxy[NBLK * EDIM];

// ---------------------------------------------------------------------------
// K1: logits = x @ W, softmax, argmax, proxy sums.
// LDS-optimized + double-buffered:
//  - 32 chunks of 32 m; next chunk LDG'd into regs during current compute.
//  - W staged interleaved per mm-pair: (e0m0,e1m0,e0m1,e1m1) so ONE uniform
//    LDS.128 (ulonglong2) yields two f32x2 operands: 8 LDS wf / 1024 MACs.
//  - Per-(token,expert) accumulation strictly sequential in m -> logits
//    bit-identical to the R6 kernel (same FFMA2 order).
// Warp w -> experts [8w,8w+8) (pairs 4w..4w+3), lane l -> tokens {l, l+32}.
// ---------------------------------------------------------------------------
__global__ __launch_bounds__(256, 2)
void k_gemm(const float* __restrict__ x, const float* __restrict__ Wt) {
    __shared__ __align__(16) float xls[2][64 * 33];   // x chunks (pitch 33)
    __shared__ __align__(16) float wv[2][16 * 128];   // W interleaved chunks
    __shared__ float isum[64];

    const int tid = threadIdx.x;
    const int w = tid >> 5;
    const int l = tid & 31;
    const int tb = blockIdx.x * 64;

    ull acc[2][4] = {};

    // staging index precompute
    const int t0 = tid >> 3, q0 = tid & 7;          // x: f4 slots tid, tid+256
    const int mp0 = tid >> 5, p0 = tid & 31;        // W: f4 slots tid, tid+256

    float4 xr0, xr1;
    float2 wa0, wb0, wa1, wb1;

    // ---- stage chunk 0 ----
    {
        const int mb = 0;
        xr0 = *(const float4*)(x + (size_t)(tb + t0) * MDIM + mb + q0 * 4);
        xr1 = *(const float4*)(x + (size_t)(tb + t0 + 32) * MDIM + mb + q0 * 4);
        wa0 = *(const float2*)(Wt + (size_t)(mb + 2 * mp0) * EDIM + 2 * p0);
        wb0 = *(const float2*)(Wt + (size_t)(mb + 2 * mp0 + 1) * EDIM + 2 * p0);
        wa1 = *(const float2*)(Wt + (size_t)(mb + 2 * (mp0 + 8)) * EDIM + 2 * p0);
        wb1 = *(const float2*)(Wt + (size_t)(mb + 2 * (mp0 + 8) + 1) * EDIM + 2 * p0);
        float* xd = &xls[0][0];
        float* da = &xd[t0 * 33 + q0 * 4];
        da[0] = xr0.x; da[1] = xr0.y; da[2] = xr0.z; da[3] = xr0.w;
        float* db = &xd[(t0 + 32) * 33 + q0 * 4];
        db[0] = xr1.x; db[1] = xr1.y; db[2] = xr1.z; db[3] = xr1.w;
        float4* wd = (float4*)&wv[0][0];
        wd[tid]       = make_float4(wa0.x, wa0.y, wb0.x, wb0.y);
        wd[tid + 256] = make_float4(wa1.x, wa1.y, wb1.x, wb1.y);
    }
    __syncthreads();

    for (int ch = 0; ch < 32; ++ch) {
        const int cb = ch & 1, nb = (ch + 1) & 1;

        if (ch < 31) {     // prefetch next chunk into regs (overlaps compute)
            const int mb = (ch + 1) * 32;
            xr0 = *(const float4*)(x + (size_t)(tb + t0) * MDIM + mb + q0 * 4);
            xr1 = *(const float4*)(x + (size_t)(tb + t0 + 32) * MDIM + mb + q0 * 4);
            wa0 = *(const float2*)(Wt + (size_t)(mb + 2 * mp0) * EDIM + 2 * p0);
            wb0 = *(const float2*)(Wt + (size_t)(mb + 2 * mp0 + 1) * EDIM + 2 * p0);
            wa1 = *(const float2*)(Wt + (size_t)(mb + 2 * (mp0 + 8)) * EDIM + 2 * p0);
            wb1 = *(const float2*)(Wt + (size_t)(mb + 2 * (mp0 + 8) + 1) * EDIM + 2 * p0);
        }

        // compute current chunk: 16 mm-pairs
        const float* xc = &xls[cb][0];
#pragma unroll 8
        for (int mp = 0; mp < 16; ++mp) {
            float xa0 = xc[l * 33 + 2 * mp];
            float xa1 = xc[l * 33 + 2 * mp + 1];
            float xb0 = xc[(l + 32) * 33 + 2 * mp];
            float xb1 = xc[(l + 32) * 33 + 2 * mp + 1];
            ull xa20, xa21, xb20, xb21;
            asm("mov.b64 %0, {%1, %1};" : "=l"(xa20) : "f"(xa0));
            asm("mov.b64 %0, {%1, %1};" : "=l"(xa21) : "f"(xa1));
            asm("mov.b64 %0, {%1, %1};" : "=l"(xb20) : "f"(xb0));
            asm("mov.b64 %0, {%1, %1};" : "=l"(xb21) : "f"(xb1));
            const ulonglong2* wp = (const ulonglong2*)&wv[cb][mp * 128 + w * 16];
#pragma unroll
            for (int j = 0; j < 4; ++j) {
                ulonglong2 ww = wp[j];               // uniform LDS.128
                asm("fma.rn.f32x2 %0, %1, %2, %0;" : "+l"(acc[0][j]) : "l"(ww.x), "l"(xa20));
                asm("fma.rn.f32x2 %0, %1, %2, %0;" : "+l"(acc[0][j]) : "l"(ww.y), "l"(xa21));
                asm("fma.rn.f32x2 %0, %1, %2, %0;" : "+l"(acc[1][j]) : "l"(ww.x), "l"(xb20));
                asm("fma.rn.f32x2 %0, %1, %2, %0;" : "+l"(acc[1][j]) : "l"(ww.y), "l"(xb21));
            }
        }

        if (ch < 31) {     // store prefetched regs into the other buffer
            float* xd = &xls[nb][0];
            float* da = &xd[t0 * 33 + q0 * 4];
            da[0] = xr0.x; da[1] = xr0.y; da[2] = xr0.z; da[3] = xr0.w;
            float* db = &xd[(t0 + 32) * 33 + q0 * 4];
            db[0] = xr1.x; db[1] = xr1.y; db[2] = xr1.z; db[3] = xr1.w;
            float4* wd = (float4*)&wv[nb][0];
            wd[tid]       = make_float4(wa0.x, wa0.y, wb0.x, wb0.y);
            wd[tid + 256] = make_float4(wa1.x, wa1.y, wb1.x, wb1.y);
        }
        __syncthreads();
    }

    // logits -> smem (reuse xls flat, pitch 65: 4160 <= 4224 floats)
    float* lg = &xls[0][0];
#pragma unroll
    for (int tt = 0; tt < 2; ++tt) {
        int t = l + 32 * tt;
#pragma unroll
        for (int p = 0; p < 4; ++p) {
            float lo, hi;
            asm("mov.b64 {%0, %1}, %2;" : "=f"(lo), "=f"(hi) : "l"(acc[tt][p]));
            lg[t * 65 + w * 8 + 2 * p]     = lo;
            lg[t * 65 + w * 8 + 2 * p + 1] = hi;
        }
    }
    __syncthreads();

    if (tid < 64) {
        const int t = tid;
        float mx = -1e30f; int am = 0;
        for (int e = 0; e < EDIM; ++e) {
            float v = lg[t * 65 + e];
            if (v > mx) { mx = v; am = e; }     // first-max semantics
        }
        float sm = 0.0f;
        for (int e = 0; e < EDIM; ++e) {
            float p = expf(lg[t * 65 + e] - mx);
            lg[t * 65 + e] = p;
            sm += p;
        }
        float inv = 1.0f / sm;
        isum[t] = inv;
        g_idx[tb + t]  = am;
        g_gate[tb + t] = inv;
    }
    __syncthreads();

    if (tid < 64) {
        const int e = tid;
        float s = 0.0f;
        for (int t = 0; t < 64; ++t) s += lg[t * 65 + e] * isum[t];
        g_proxy[blockIdx.x * 64 + e] = s;
    }
}

// ---------------------------------------------------------------------------
// K2: exclusive running position within each (group, expert). (R6 exact)
// ---------------------------------------------------------------------------
__global__ __launch_bounds__(1024, 1)
void k_pos() {
    __shared__ int idx_s[2048];
    __shared__ int cnt_s[16 * 64];
    __shared__ int pos_s[2048];

    const int g = blockIdx.x;
    const int tid = threadIdx.x;

    idx_s[tid]        = g_idx[g * 2048 + tid];
    idx_s[tid + 1024] = g_idx[g * 2048 + tid + 1024];
    __syncthreads();

    const int c = tid >> 6;
    const int e = tid & 63;

    int cnt = 0;
#pragma unroll 8
    for (int i = 0; i < 128; ++i) cnt += (idx_s[c * 128 + i] == e);
    cnt_s[c * 64 + e] = cnt;
    __syncthreads();

    int pre = 0;
    for (int cc = 0; cc < c; ++cc) pre += cnt_s[cc * 64 + e];
    if (c == 15) g_counts[g * 64 + e] = pre + cnt;

    int run = pre;
#pragma unroll 4
    for (int i = 0; i < 128; ++i) {
        int s = c * 128 + i;
        if (idx_s[s] == e) pos_s[s] = run++;
    }
    __syncthreads();

    g_pos[g * 2048 + tid]        = pos_s[tid];
    g_pos[g * 2048 + tid + 1024] = pos_s[tid + 1024];
}

// ---------------------------------------------------------------------------
// K3: fused fill + scatter + aux (R6 exact — the 146.2us version).
// Block r in [0, 2*TTOT): one 40KB contiguous output row, nonzero patched
// inline, streaming stores. Block 2*TTOT: aux loss.
// ---------------------------------------------------------------------------
__global__ __launch_bounds__(256, 8)
void k_fill(float* __restrict__ out, int C, size_t N) {
    const int r = blockIdx.x;
    const int tid = threadIdx.x;

    if (r < 2 * TTOT) {
        const int sec = (r >= TTOT);
        const int t = sec ? r - TTOT : r;

        const int p = g_pos[t];
        const int tgt = (p < C) ? (g_idx[t] * C + p) : -1;
        const float val = sec ? 1.0f : g_gate[t];
        const int tf4 = tgt >> 2;

        float4* row = (float4*)(out + (size_t)sec * N + (size_t)t * (size_t)(EDIM * C));
        const int nf4 = (EDIM * C) >> 2;                 // 2560 for C=160

        for (int f = tid; f < nf4; f += 256) {
            float4 v = make_float4(0.f, 0.f, 0.f, 0.f);
            if (f == tf4) ((float*)&v)[tgt & 3] = val;
            __stcs(row + f, v);
        }
    } else {
        __shared__ float red[256];
        const int g = tid >> 6;
        const int e = tid & 63;
        float px = 0.0f;
        for (int b = 0; b < 32; ++b) px += g_proxy[(g * 32 + b) * 64 + e];
        const float denom = 1.0f + 1e-6f;
        float d1 = ((float)g_counts[g * 64 + e] / (float)SDIM) / denom;
        float dp = (px / (float)SDIM) / denom;
        red[tid] = d1 * dp;
        __syncthreads();
        for (int s = 128; s > 0; s >>= 1) {
            if (tid < s) red[tid] += red[tid + s];
            __syncthreads();
        }
        if (tid == 0)
            out[2 * N] = (red[0] / 256.0f) * ((float)EDIM * (float)EDIM * 0.01f);
    }
}

// ---------------------------------------------------------------------------
extern "C" void kernel_launch(void* const* d_in, const int* in_sizes, int n_in,
                              void* d_out, int out_size) {
    const float* x  = (const float*)d_in[0];
    const float* Wt = (const float*)d_in[1];
    float* out = (float*)d_out;

    size_t N = ((size_t)out_size - 1) / 2;
    int C = (int)(N / ((size_t)TTOT * EDIM));   // 160

    k_gemm<<<NBLK, 256>>>(x, Wt);
    k_pos<<<GDIM, 1024>>>();
    k_fill<<<2 * TTOT + 1, 256>>>(out, C, N);
}